// round 5
// baseline (speedup 1.0000x reference)
#include <cuda_runtime.h>
#include <math.h>

#define Bq 2
#define NH 8
#define Gh 4
#define Tt 2048
#define Nn 2048
#define Dd 512
#define HALF (Nn/2)

#define SCALE 0.022097086912079612f   // 2048^-0.5

#define SZ_Q     ((long long)Bq * NH * Tt * Nn)   // 67,108,864
#define SZ_V     ((long long)Bq * 1  * Tt * Dd)   //  2,097,152
#define SZ_STATE ((long long)Bq * NH * Nn * Dd)   // 16,777,216
#define SZ_LAM   ((long long)Gh)                  //          4

// ---------------- scratch (device globals, no allocation) ----------------
__device__ __align__(16) float g_cos[Tt * HALF];                       //   8 MB
__device__ __align__(16) float g_sin[Tt * HALF];                       //   8 MB
__device__ __align__(16) float g_QR[(size_t)Bq * NH * Tt * Nn];        // 268 MB
__device__ __align__(16) float g_P [(size_t)Bq * NH * Tt * Nn];        // 268 MB (exclusive prefix of QR over t)
__device__ __align__(16) float g_rows[(size_t)Bq * Gh * Tt];           //  64 KB (masked diff-score row sums)

// ---------------- K1: rope tables (double precision) ----------------
__global__ void k_tables(const int* pos_offset_p) {
    int idx = blockIdx.x * blockDim.x + threadIdx.x;
    if (idx >= Tt * HALF) return;
    int t = idx / HALF;
    int c = idx % HALF;
    int off = pos_offset_p ? *pos_offset_p : 0;
    double freq = 1.0 / pow(65536.0, (double)(2 * c) / (double)Nn) / (2.0 * M_PI);
    double pos  = (double)(off + t);
    double ang  = fmod(pos * freq, 1.0) * (2.0 * M_PI);
    g_cos[idx] = (float)cos(ang);
    g_sin[idx] = (float)sin(ang);
}

// ---------------- K2: RoPE(Q) -> g_QR ----------------
__global__ void k_rope(const float* __restrict__ Q) {
    long long idx = (long long)blockIdx.x * blockDim.x + threadIdx.x; // pair index
    const long long TOT = (long long)Bq * NH * Tt * HALF;
    if (idx >= TOT) return;
    int c = (int)(idx % HALF);
    long long r = idx / HALF;
    int t = (int)(r % Tt);
    float2 q = ((const float2*)Q)[idx];
    float cs = g_cos[t * HALF + c];
    float sn = g_sin[t * HALF + c];
    float2 o;
    o.x = q.x * cs - q.y * sn;
    o.y = q.x * sn + q.y * cs;
    ((float2*)g_QR)[idx] = o;
}

// ---------------- K3: exclusive prefix sum over t, per (bh, n) ----------------
__global__ void k_prefix() {
    int bh = blockIdx.y;                               // 0..15
    int n  = blockIdx.x * blockDim.x + threadIdx.x;    // 0..2047
    const float* src = g_QR + (size_t)bh * Tt * Nn + n;
    float*       dst = g_P  + (size_t)bh * Tt * Nn + n;
    float acc = 0.f;
#pragma unroll 4
    for (int t = 0; t < Tt; t++) {
        dst[(size_t)t * Nn] = acc;
        acc += src[(size_t)t * Nn];
    }
}

// ---------------- K4: rows[bg,t] = SCALE*(QR1[t].P1[t] - lam*QR2[t].P2[t]) ----------------
__global__ void __launch_bounds__(256) k_rowsum(const float* __restrict__ lambda_param) {
    int bg = blockIdx.y;                 // 0..7  (b*Gh+g)
    int g  = bg % Gh;
    int w    = threadIdx.x >> 5;
    int lane = threadIdx.x & 31;
    int t = blockIdx.x * 8 + w;          // 256 blocks * 8 warps = 2048

    // head 2g of batch b lives at index 2*bg (NH = 2*Gh)
    const float* q1 = g_QR + ((size_t)bg * 2) * Tt * Nn + (size_t)t * Nn;
    const float* q2 = q1 + (size_t)Tt * Nn;
    const float* p1 = g_P  + ((size_t)bg * 2) * Tt * Nn + (size_t)t * Nn;
    const float* p2 = p1 + (size_t)Tt * Nn;

    float r1 = 0.f, r2 = 0.f;
    for (int n = lane; n < Nn; n += 32) {
        r1 += q1[n] * p1[n];
        r2 += q2[n] * p2[n];
    }
#pragma unroll
    for (int o = 16; o; o >>= 1) {
        r1 += __shfl_xor_sync(0xffffffffu, r1, o);
        r2 += __shfl_xor_sync(0xffffffffu, r2, o);
    }
    if (lane == 0) {
        float lam = 1.f / (1.f + expf(-lambda_param[g]));
        g_rows[(size_t)bg * Tt + t] = SCALE * (r1 - lam * r2);
    }
}

// ---------------- K5: out = QR @ state + rows[t]*V[t,d]  (fused) ----------------
__global__ void __launch_bounds__(256) k_out(const float* __restrict__ state,
                                             const float* __restrict__ V,
                                             float* __restrict__ out) {
    __shared__ float As[16][129];
    __shared__ float Bs[16][129];

    int it = blockIdx.x >> 2;
    int dt = blockIdx.x & 3;
    int bh = blockIdx.y;              // 0..15
    int b  = bh >> 3;
    int h  = bh & 7;

    const float* A  = g_QR + (size_t)bh * Tt * Nn;
    const float* Bb = state + (size_t)bh * Nn * Dd;

    int tid = threadIdx.x;
    int tx = tid & 15, ty = tid >> 4;
    int row0 = it * 128, col0 = dt * 128;

    float acc[8][8];
#pragma unroll
    for (int i = 0; i < 8; i++)
#pragma unroll
        for (int j = 0; j < 8; j++) acc[i][j] = 0.f;

    for (int k0 = 0; k0 < Nn; k0 += 16) {
#pragma unroll
        for (int j = 0; j < 8; j++) {
            int idx = tid + j * 256;
            int m = idx >> 4, k = idx & 15;
            As[k][m] = A[(size_t)(row0 + m) * Nn + k0 + k];
        }
#pragma unroll
        for (int j = 0; j < 8; j++) {
            int idx = tid + j * 256;
            int kk = idx >> 7, n = idx & 127;
            Bs[kk][n] = Bb[(size_t)(k0 + kk) * Dd + col0 + n];
        }
        __syncthreads();
#pragma unroll
        for (int kk = 0; kk < 16; kk++) {
            float a[8], bb[8];
#pragma unroll
            for (int i = 0; i < 8; i++) a[i] = As[kk][ty * 8 + i];
#pragma unroll
            for (int j = 0; j < 8; j++) bb[j] = Bs[kk][tx * 8 + j];
#pragma unroll
            for (int i = 0; i < 8; i++)
#pragma unroll
                for (int j = 0; j < 8; j++) acc[i][j] += a[i] * bb[j];
        }
        __syncthreads();
    }

    const float* rows = g_rows + ((size_t)(b * Gh + (h >> 1))) * Tt;
    const float* Vb   = V + (size_t)b * Tt * Dd;
    float* o = out + ((size_t)bh * Tt) * Dd;
#pragma unroll
    for (int i = 0; i < 8; i++) {
        int t = row0 + ty * 8 + i;
        float r = rows[t];
#pragma unroll
        for (int j = 0; j < 8; j++) {
            int d = col0 + tx * 8 + j;
            o[(size_t)t * Dd + d] = acc[i][j] + r * Vb[(size_t)t * Dd + d];
        }
    }
}

// ---------------- K6: new_state = state + SCALE * QR^T @ V ----------------
__global__ void __launch_bounds__(256) k_newstate(const float* __restrict__ V,
                                                  const float* __restrict__ state,
                                                  float* __restrict__ ns_out) {
    __shared__ float As[16][129];
    __shared__ float Bs[16][129];

    int nt = blockIdx.x >> 2;        // 0..15 (N tiles)
    int dt = blockIdx.x & 3;         // 0..3 (D tiles)
    int bh = blockIdx.y;             // 0..15
    int b  = bh >> 3;

    const float* A  = g_QR + (size_t)bh * Tt * Nn;   // [t][n]
    const float* Bv = V + (size_t)b * Tt * Dd;       // [t][d]

    int tid = threadIdx.x;
    int tx = tid & 15, ty = tid >> 4;
    int row0 = nt * 128, col0 = dt * 128;

    float acc[8][8];
#pragma unroll
    for (int i = 0; i < 8; i++)
#pragma unroll
        for (int j = 0; j < 8; j++) acc[i][j] = 0.f;

    for (int k0 = 0; k0 < Tt; k0 += 16) {
#pragma unroll
        for (int j = 0; j < 8; j++) {
            int idx = tid + j * 256;
            int kk = idx >> 7, m = idx & 127;
            As[kk][m] = A[(size_t)(k0 + kk) * Nn + row0 + m];
        }
#pragma unroll
        for (int j = 0; j < 8; j++) {
            int idx = tid + j * 256;
            int kk = idx >> 7, n = idx & 127;
            Bs[kk][n] = Bv[(size_t)(k0 + kk) * Dd + col0 + n];
        }
        __syncthreads();
#pragma unroll
        for (int kk = 0; kk < 16; kk++) {
            float a[8], bb[8];
#pragma unroll
            for (int i = 0; i < 8; i++) a[i] = As[kk][ty * 8 + i];
#pragma unroll
            for (int j = 0; j < 8; j++) bb[j] = Bs[kk][tx * 8 + j];
#pragma unroll
            for (int i = 0; i < 8; i++)
#pragma unroll
                for (int j = 0; j < 8; j++) acc[i][j] += a[i] * bb[j];
        }
        __syncthreads();
    }

    const float* st = state + (size_t)bh * Nn * Dd;
    float* o = ns_out + (size_t)bh * Nn * Dd;
#pragma unroll
    for (int i = 0; i < 8; i++) {
        int n = row0 + ty * 8 + i;
#pragma unroll
        for (int j = 0; j < 8; j++) {
            int d = col0 + tx * 8 + j;
            size_t off = (size_t)n * Dd + d;
            o[off] = st[off] + SCALE * acc[i][j];
        }
    }
}

// ---------------- launch ----------------
extern "C" void kernel_launch(void* const* d_in, const int* in_sizes, int n_in,
                              void* d_out, int out_size) {
    const float* Q     = nullptr;
    const float* V     = nullptr;
    const float* state = nullptr;
    const float* lam   = nullptr;
    const int*   pos   = nullptr;

    for (int i = 0; i < n_in; i++) {
        long long s = (long long)in_sizes[i];
        if      (s == SZ_Q)     Q     = (const float*)d_in[i];
        else if (s == SZ_V)     V     = (const float*)d_in[i];
        else if (s == SZ_STATE) state = (const float*)d_in[i];
        else if (s == SZ_LAM)   lam   = (const float*)d_in[i];
        else if (s == 1)        pos   = (const int*)d_in[i];
    }
    if (!Q     && n_in > 0) Q     = (const float*)d_in[0];
    if (!V     && n_in > 1) V     = (const float*)d_in[1];
    if (!state && n_in > 2) state = (const float*)d_in[2];
    if (!lam   && n_in > 3) lam   = (const float*)d_in[3];

    // d_out layout: [output, new_state]  (reference-return order; established
    // by the R3/R4 bit-identical rel_err fingerprint)
    const size_t SEG = (size_t)16777216;
    float* out_t  = (float*)d_out;        // segment 0: output
    float* ns_out = (float*)d_out + SEG;  // segment 1: new_state

    k_tables<<<(Tt * HALF + 255) / 256, 256>>>(pos);
    {
        long long tot = (long long)Bq * NH * Tt * HALF;
        k_rope<<<(unsigned)((tot + 255) / 256), 256>>>(Q);
    }
    k_prefix<<<dim3(Nn / 256, Bq * NH), 256>>>();
    k_rowsum<<<dim3(Tt / 8, Bq * Gh), 256>>>(lam);
    k_out<<<dim3(64, Bq * NH), 256>>>(state, V, out_t);
    k_newstate<<<dim3(64, Bq * NH), 256>>>(V, state, ns_out);
}

// round 6
// speedup vs baseline: 1.6391x; 1.6391x over previous
#include <cuda_runtime.h>
#include <cuda_bf16.h>
#include <math.h>
#include <stdint.h>

#define Bq 2
#define NH 8
#define Gh 4
#define Tt 2048
#define Nn 2048
#define Dd 512
#define HALF (Nn/2)

#define SCALE 0.022097086912079612f   // 2048^-0.5

#define SZ_Q     ((long long)Bq * NH * Tt * Nn)   // 67,108,864
#define SZ_V     ((long long)Bq * 1  * Tt * Dd)   //  2,097,152
#define SZ_STATE ((long long)Bq * NH * Nn * Dd)   // 16,777,216
#define SZ_LAM   ((long long)Gh)                  //          4

// ---------------- scratch (device globals, no allocation) ----------------
__device__ __align__(16) float g_cos[Tt * HALF];                       //   8 MB
__device__ __align__(16) float g_sin[Tt * HALF];                       //   8 MB
__device__ __align__(16) float g_QR[(size_t)Bq * NH * Tt * Nn];        // 268 MB
__device__ __align__(16) float g_P [(size_t)Bq * NH * Tt * Nn];        // 268 MB
__device__ __align__(16) float g_rows[(size_t)Bq * Gh * Tt];           //  64 KB

// ---------------- K1: rope tables (double precision) ----------------
__global__ void k_tables(const int* pos_offset_p) {
    int idx = blockIdx.x * blockDim.x + threadIdx.x;
    if (idx >= Tt * HALF) return;
    int t = idx / HALF;
    int c = idx % HALF;
    int off = pos_offset_p ? *pos_offset_p : 0;
    // theta^(q/N) = 2^(16*2c/2048) = 2^(c/64)
    double freq = exp2(-(double)c / 64.0) / (2.0 * M_PI);
    double pos  = (double)(off + t);
    double ang  = fmod(pos * freq, 1.0) * (2.0 * M_PI);
    g_cos[idx] = (float)cos(ang);
    g_sin[idx] = (float)sin(ang);
}

// ---------------- K2: RoPE(Q) -> g_QR ----------------
__global__ void k_rope(const float* __restrict__ Q) {
    long long idx = (long long)blockIdx.x * blockDim.x + threadIdx.x;
    const long long TOT = (long long)Bq * NH * Tt * HALF;
    if (idx >= TOT) return;
    int c = (int)(idx % HALF);
    long long r = idx / HALF;
    int t = (int)(r % Tt);
    float2 q = ((const float2*)Q)[idx];
    float cs = g_cos[t * HALF + c];
    float sn = g_sin[t * HALF + c];
    float2 o;
    o.x = q.x * cs - q.y * sn;
    o.y = q.x * sn + q.y * cs;
    ((float2*)g_QR)[idx] = o;
}

// ---------------- K3: exclusive prefix sum over t, per (bh, n) ----------------
__global__ void k_prefix() {
    int bh = blockIdx.y;
    int n  = blockIdx.x * blockDim.x + threadIdx.x;
    const float* src = g_QR + (size_t)bh * Tt * Nn + n;
    float*       dst = g_P  + (size_t)bh * Tt * Nn + n;
    float acc = 0.f;
#pragma unroll 4
    for (int t = 0; t < Tt; t++) {
        dst[(size_t)t * Nn] = acc;
        acc += src[(size_t)t * Nn];
    }
}

// ---------------- K4: rows[bg,t] = SCALE*(QR1[t].P1[t] - lam*QR2[t].P2[t]) ----------------
__global__ void __launch_bounds__(256) k_rowsum(const float* __restrict__ lambda_param) {
    int bg = blockIdx.y;
    int g  = bg % Gh;
    int w    = threadIdx.x >> 5;
    int lane = threadIdx.x & 31;
    int t = blockIdx.x * 8 + w;

    const float* q1 = g_QR + ((size_t)bg * 2) * Tt * Nn + (size_t)t * Nn;
    const float* q2 = q1 + (size_t)Tt * Nn;
    const float* p1 = g_P  + ((size_t)bg * 2) * Tt * Nn + (size_t)t * Nn;
    const float* p2 = p1 + (size_t)Tt * Nn;

    float r1 = 0.f, r2 = 0.f;
    for (int n = lane; n < Nn; n += 32) {
        r1 += q1[n] * p1[n];
        r2 += q2[n] * p2[n];
    }
#pragma unroll
    for (int o = 16; o; o >>= 1) {
        r1 += __shfl_xor_sync(0xffffffffu, r1, o);
        r2 += __shfl_xor_sync(0xffffffffu, r2, o);
    }
    if (lane == 0) {
        float lam = 1.f / (1.f + expf(-lambda_param[g]));
        g_rows[(size_t)bg * Tt + t] = SCALE * (r1 - lam * r2);
    }
}

// ---------------- tensor-core GEMM machinery (bf16 3-pass split) ----------------
#define KPAD 40   // bf16 elements per smem row (conflict-free fragment loads)

#define MMA_BF16(C, A0, A1, A2, A3, B0, B1)                                   \
    asm volatile("mma.sync.aligned.m16n8k16.row.col.f32.bf16.bf16.f32 "       \
                 "{%0,%1,%2,%3}, {%4,%5,%6,%7}, {%8,%9}, {%0,%1,%2,%3};"      \
                 : "+f"((C)[0]), "+f"((C)[1]), "+f"((C)[2]), "+f"((C)[3])     \
                 : "r"(A0), "r"(A1), "r"(A2), "r"(A3), "r"(B0), "r"(B1))

__device__ __forceinline__ void split_bf16(float x, __nv_bfloat16& hi, __nv_bfloat16& lo) {
    hi = __float2bfloat16(x);
    lo = __float2bfloat16(x - __bfloat162float(hi));
}

// ---------------- K5: out = QR @ state + rows[t]*V[t,d] ----------------
// per head: M=2048(t) x N=512(d) x K=2048(n). grid.x = 16 mtiles * 4 ntiles (n inner), grid.y = bh
__global__ void __launch_bounds__(256) k_out_mma(const float* __restrict__ state,
                                                 const float* __restrict__ V,
                                                 float* __restrict__ out) {
    __shared__ __nv_bfloat16 sAhi[128][KPAD], sAlo[128][KPAD];
    __shared__ __nv_bfloat16 sBhi[128][KPAD], sBlo[128][KPAD];

    int bh = blockIdx.y;
    int b = bh >> 3, h = bh & 7;
    int row0 = (blockIdx.x >> 2) * 128;
    int col0 = (blockIdx.x & 3) * 128;

    const float* A = g_QR + (size_t)bh * Tt * Nn;   // [t][n]
    const float* B = state + (size_t)bh * Nn * Dd;  // [n][d]

    int tid = threadIdx.x, lane = tid & 31, w = tid >> 5;
    int wm = w >> 1, wn = w & 1;
    int lq = lane >> 2;            // lane/4
    int lr = (lane & 3) * 2;       // (lane%4)*2

    float c[2][8][4];
#pragma unroll
    for (int mt = 0; mt < 2; mt++)
#pragma unroll
        for (int nt = 0; nt < 8; nt++)
#pragma unroll
            for (int q = 0; q < 4; q++) c[mt][nt][q] = 0.f;

    for (int k0 = 0; k0 < Nn; k0 += 32) {
        // A tile 128x32, direct layout [m][k]
#pragma unroll
        for (int i = 0; i < 16; i++) {
            int idx = tid + i * 256;
            int m = idx >> 5, k = idx & 31;
            float x = A[(size_t)(row0 + m) * Nn + k0 + k];
            split_bf16(x, sAhi[m][k], sAlo[m][k]);
        }
        // B tile 32x128 -> transpose to [d][k]
#pragma unroll
        for (int i = 0; i < 8; i++) {
            int idx = tid + i * 256;
            int d = idx & 127, kp = idx >> 7;    // kp 0..15
            int k = kp * 2;
            float x0 = B[(size_t)(k0 + k) * Dd + col0 + d];
            float x1 = B[(size_t)(k0 + k + 1) * Dd + col0 + d];
            __nv_bfloat162 hp, lp;
            split_bf16(x0, hp.x, lp.x);
            split_bf16(x1, hp.y, lp.y);
            *(__nv_bfloat162*)&sBhi[d][k] = hp;
            *(__nv_bfloat162*)&sBlo[d][k] = lp;
        }
        __syncthreads();

#pragma unroll
        for (int kk = 0; kk < 32; kk += 16) {
            uint32_t ah[2][4], al[2][4];
#pragma unroll
            for (int mt = 0; mt < 2; mt++) {
                int r = wm * 32 + mt * 16 + lq;
                int kc = kk + lr;
                ah[mt][0] = *(const uint32_t*)&sAhi[r][kc];
                ah[mt][1] = *(const uint32_t*)&sAhi[r + 8][kc];
                ah[mt][2] = *(const uint32_t*)&sAhi[r][kc + 8];
                ah[mt][3] = *(const uint32_t*)&sAhi[r + 8][kc + 8];
                al[mt][0] = *(const uint32_t*)&sAlo[r][kc];
                al[mt][1] = *(const uint32_t*)&sAlo[r + 8][kc];
                al[mt][2] = *(const uint32_t*)&sAlo[r][kc + 8];
                al[mt][3] = *(const uint32_t*)&sAlo[r + 8][kc + 8];
            }
#pragma unroll
            for (int nt = 0; nt < 8; nt++) {
                int n = wn * 64 + nt * 8 + lq;
                int kc = kk + lr;
                uint32_t b0h = *(const uint32_t*)&sBhi[n][kc];
                uint32_t b1h = *(const uint32_t*)&sBhi[n][kc + 8];
                uint32_t b0l = *(const uint32_t*)&sBlo[n][kc];
                uint32_t b1l = *(const uint32_t*)&sBlo[n][kc + 8];
#pragma unroll
                for (int mt = 0; mt < 2; mt++) {
                    MMA_BF16(c[mt][nt], ah[mt][0], ah[mt][1], ah[mt][2], ah[mt][3], b0h, b1h);
                    MMA_BF16(c[mt][nt], ah[mt][0], ah[mt][1], ah[mt][2], ah[mt][3], b0l, b1l);
                    MMA_BF16(c[mt][nt], al[mt][0], al[mt][1], al[mt][2], al[mt][3], b0h, b1h);
                }
            }
        }
        __syncthreads();
    }

    // epilogue: + rows[t] * V[t][d]
    const float* rows = g_rows + ((size_t)(b * Gh + (h >> 1))) * Tt;
    const float* Vb   = V + (size_t)b * Tt * Dd;
    float* o = out + (size_t)bh * Tt * Dd;
#pragma unroll
    for (int mt = 0; mt < 2; mt++) {
#pragma unroll
        for (int half = 0; half < 2; half++) {
            int r = row0 + wm * 32 + mt * 16 + lq + half * 8;
            float rowv = rows[r];
            const float2* vrow = (const float2*)&Vb[(size_t)r * Dd];
            float2* orow = (float2*)&o[(size_t)r * Dd];
#pragma unroll
            for (int nt = 0; nt < 8; nt++) {
                int cc = col0 + wn * 64 + nt * 8 + lr;
                float2 v = vrow[cc >> 1];
                float2 res;
                res.x = c[mt][nt][half * 2 + 0] + rowv * v.x;
                res.y = c[mt][nt][half * 2 + 1] + rowv * v.y;
                orow[cc >> 1] = res;
            }
        }
    }
}

// ---------------- K6: new_state = state + SCALE * QR^T @ V ----------------
// per head: M=2048(n) x N=512(d) x K=2048(t); A = QR^T (transposed loads)
__global__ void __launch_bounds__(256) k_newstate_mma(const float* __restrict__ V,
                                                      const float* __restrict__ state,
                                                      float* __restrict__ ns_out) {
    __shared__ __nv_bfloat16 sAhi[128][KPAD], sAlo[128][KPAD];
    __shared__ __nv_bfloat16 sBhi[128][KPAD], sBlo[128][KPAD];

    int bh = blockIdx.y;
    int b = bh >> 3;
    int row0 = (blockIdx.x >> 2) * 128;   // n tile
    int col0 = (blockIdx.x & 3) * 128;    // d tile

    const float* A  = g_QR + (size_t)bh * Tt * Nn;  // [t][n]
    const float* Bv = V + (size_t)b * Tt * Dd;      // [t][d]

    int tid = threadIdx.x, lane = tid & 31, w = tid >> 5;
    int wm = w >> 1, wn = w & 1;
    int lq = lane >> 2;
    int lr = (lane & 3) * 2;

    float c[2][8][4];
#pragma unroll
    for (int mt = 0; mt < 2; mt++)
#pragma unroll
        for (int nt = 0; nt < 8; nt++)
#pragma unroll
            for (int q = 0; q < 4; q++) c[mt][nt][q] = 0.f;

    for (int k0 = 0; k0 < Tt; k0 += 32) {
        // A tile: [k=t 32][m=n 128] from QR -> transpose to [n][t]
#pragma unroll
        for (int i = 0; i < 8; i++) {
            int idx = tid + i * 256;
            int n = idx & 127, kp = idx >> 7;
            int t = k0 + kp * 2;
            float x0 = A[(size_t)t * Nn + row0 + n];
            float x1 = A[(size_t)(t + 1) * Nn + row0 + n];
            __nv_bfloat162 hp, lp;
            split_bf16(x0, hp.x, lp.x);
            split_bf16(x1, hp.y, lp.y);
            *(__nv_bfloat162*)&sAhi[n][kp * 2] = hp;
            *(__nv_bfloat162*)&sAlo[n][kp * 2] = lp;
        }
        // B tile: [k=t 32][d 128] from V -> transpose to [d][t]
#pragma unroll
        for (int i = 0; i < 8; i++) {
            int idx = tid + i * 256;
            int d = idx & 127, kp = idx >> 7;
            int t = k0 + kp * 2;
            float x0 = Bv[(size_t)t * Dd + col0 + d];
            float x1 = Bv[(size_t)(t + 1) * Dd + col0 + d];
            __nv_bfloat162 hp, lp;
            split_bf16(x0, hp.x, lp.x);
            split_bf16(x1, hp.y, lp.y);
            *(__nv_bfloat162*)&sBhi[d][kp * 2] = hp;
            *(__nv_bfloat162*)&sBlo[d][kp * 2] = lp;
        }
        __syncthreads();

#pragma unroll
        for (int kk = 0; kk < 32; kk += 16) {
            uint32_t ah[2][4], al[2][4];
#pragma unroll
            for (int mt = 0; mt < 2; mt++) {
                int r = wm * 32 + mt * 16 + lq;
                int kc = kk + lr;
                ah[mt][0] = *(const uint32_t*)&sAhi[r][kc];
                ah[mt][1] = *(const uint32_t*)&sAhi[r + 8][kc];
                ah[mt][2] = *(const uint32_t*)&sAhi[r][kc + 8];
                ah[mt][3] = *(const uint32_t*)&sAhi[r + 8][kc + 8];
                al[mt][0] = *(const uint32_t*)&sAlo[r][kc];
                al[mt][1] = *(const uint32_t*)&sAlo[r + 8][kc];
                al[mt][2] = *(const uint32_t*)&sAlo[r][kc + 8];
                al[mt][3] = *(const uint32_t*)&sAlo[r + 8][kc + 8];
            }
#pragma unroll
            for (int nt = 0; nt < 8; nt++) {
                int n = wn * 64 + nt * 8 + lq;
                int kc = kk + lr;
                uint32_t b0h = *(const uint32_t*)&sBhi[n][kc];
                uint32_t b1h = *(const uint32_t*)&sBhi[n][kc + 8];
                uint32_t b0l = *(const uint32_t*)&sBlo[n][kc];
                uint32_t b1l = *(const uint32_t*)&sBlo[n][kc + 8];
#pragma unroll
                for (int mt = 0; mt < 2; mt++) {
                    MMA_BF16(c[mt][nt], ah[mt][0], ah[mt][1], ah[mt][2], ah[mt][3], b0h, b1h);
                    MMA_BF16(c[mt][nt], ah[mt][0], ah[mt][1], ah[mt][2], ah[mt][3], b0l, b1l);
                    MMA_BF16(c[mt][nt], al[mt][0], al[mt][1], al[mt][2], al[mt][3], b0h, b1h);
                }
            }
        }
        __syncthreads();
    }

    const float* st = state + (size_t)bh * Nn * Dd;
    float* o = ns_out + (size_t)bh * Nn * Dd;
#pragma unroll
    for (int mt = 0; mt < 2; mt++) {
#pragma unroll
        for (int half = 0; half < 2; half++) {
            int r = row0 + wm * 32 + mt * 16 + lq + half * 8;
            const float2* srow = (const float2*)&st[(size_t)r * Dd];
            float2* orow = (float2*)&o[(size_t)r * Dd];
#pragma unroll
            for (int nt = 0; nt < 8; nt++) {
                int cc = col0 + wn * 64 + nt * 8 + lr;
                float2 s = srow[cc >> 1];
                float2 res;
                res.x = s.x + SCALE * c[mt][nt][half * 2 + 0];
                res.y = s.y + SCALE * c[mt][nt][half * 2 + 1];
                orow[cc >> 1] = res;
            }
        }
    }
}

// ---------------- launch ----------------
extern "C" void kernel_launch(void* const* d_in, const int* in_sizes, int n_in,
                              void* d_out, int out_size) {
    const float* Q     = nullptr;
    const float* V     = nullptr;
    const float* state = nullptr;
    const float* lam   = nullptr;
    const int*   pos   = nullptr;

    for (int i = 0; i < n_in; i++) {
        long long s = (long long)in_sizes[i];
        if      (s == SZ_Q)     Q     = (const float*)d_in[i];
        else if (s == SZ_V)     V     = (const float*)d_in[i];
        else if (s == SZ_STATE) state = (const float*)d_in[i];
        else if (s == SZ_LAM)   lam   = (const float*)d_in[i];
        else if (s == 1)        pos   = (const int*)d_in[i];
    }
    if (!Q     && n_in > 0) Q     = (const float*)d_in[0];
    if (!V     && n_in > 1) V     = (const float*)d_in[1];
    if (!state && n_in > 2) state = (const float*)d_in[2];
    if (!lam   && n_in > 3) lam   = (const float*)d_in[3];

    // d_out layout: [output, new_state]
    const size_t SEG = (size_t)16777216;
    float* out_t  = (float*)d_out;
    float* ns_out = (float*)d_out + SEG;

    k_tables<<<(Tt * HALF + 255) / 256, 256>>>(pos);
    {
        long long tot = (long long)Bq * NH * Tt * HALF;
        k_rope<<<(unsigned)((tot + 255) / 256), 256>>>(Q);
    }
    k_prefix<<<dim3(Nn / 256, Bq * NH), 256>>>();
    k_rowsum<<<dim3(Tt / 8, Bq * Gh), 256>>>(lam);
    k_out_mma<<<dim3(64, Bq * NH), 256>>>(state, V, out_t);
    k_newstate_mma<<<dim3(64, Bq * NH), 256>>>(V, state, ns_out);
}